// round 5
// baseline (speedup 1.0000x reference)
#include <cuda_runtime.h>

// Problem constants (from reference)
#define BTOT   100000
#define NNB    16          // NN neighbors
#define NOB    8           // NO observations
#define SDIM   4           // SD
#define HID    64          // H
#define POUT   16          // PHI_OUT
#define DOBS   85          // 1 + (NN+1)*SD + 2*NO
#define DS_C   0.2f
#define GAM_C  0.01f

#define NB_OFF 5           // 1 + SD
#define OB_OFF 69          // 1 + (NN+1)*SD

__global__ __launch_bounds__(256) void barrier_net_kernel(
    const float* __restrict__ x,
    const float* __restrict__ phi_w1, const float* __restrict__ phi_b1,
    const float* __restrict__ phi_w2, const float* __restrict__ phi_b2,
    const float* __restrict__ obs_w1, const float* __restrict__ obs_b1,
    const float* __restrict__ obs_w2, const float* __restrict__ obs_b2,
    const float* __restrict__ rho_w1, const float* __restrict__ rho_b1,
    const float* __restrict__ rho_w2, const float* __restrict__ rho_b2,
    const float* __restrict__ psi_w1, const float* __restrict__ psi_b1,
    const float* __restrict__ psi_w2, const float* __restrict__ psi_b2,
    float* __restrict__ out)
{
    // Shared weight staging. *_w1 transposed so each hidden unit's input
    // weights are one contiguous LDS.128 (or LDS.64). *_w2 kept row-major
    // (row j contiguous over outputs).
    __shared__ __align__(16) float s_phi_w1t[HID * 4];   // [j][k]
    __shared__             float s_phi_b1 [HID];
    __shared__ __align__(16) float s_phi_w2 [HID * 16];  // [j][o]
    __shared__ __align__(16) float s_obs_w1t[HID * 2];   // [j][k]
    __shared__             float s_obs_b1 [HID];
    __shared__ __align__(16) float s_obs_w2 [HID * 16];
    __shared__ __align__(16) float s_rho_w1t[HID * 16];  // [j][k]
    __shared__             float s_rho_b1 [HID];
    __shared__ __align__(8)  float s_rho_w2 [HID * 2];
    __shared__ __align__(16) float s_psi_w1t[HID * 4];   // [j][k] k = {rho0,rho1,g0,g1}
    __shared__             float s_psi_b1 [HID];
    __shared__ __align__(8)  float s_psi_w2 [HID * 2];
    __shared__             float s_accinit[16];          // NN*phi_b2 + NO*obs_b2
    __shared__             float s_rho_b2 [2];
    __shared__             float s_psi_b2 [2];

    const int tid = threadIdx.x;

    // Cooperative weight load + transpose (tiny: ~4.3k floats total)
    for (int i = tid; i < HID * 4; i += 256) {
        int j = i >> 2, k = i & 3;
        s_phi_w1t[i] = phi_w1[k * HID + j];
        s_psi_w1t[i] = psi_w1[k * HID + j];
    }
    for (int i = tid; i < HID * 2; i += 256) {
        int j = i >> 1, k = i & 1;
        s_obs_w1t[i] = obs_w1[k * HID + j];
        s_rho_w2[i]  = rho_w2[i];
        s_psi_w2[i]  = psi_w2[i];
    }
    for (int i = tid; i < HID * 16; i += 256) {
        int j = i >> 4, k = i & 15;
        s_rho_w1t[i] = rho_w1[k * HID + j];
        s_phi_w2[i]  = phi_w2[i];
        s_obs_w2[i]  = obs_w2[i];
    }
    for (int i = tid; i < HID; i += 256) {
        s_phi_b1[i] = phi_b1[i];
        s_obs_b1[i] = obs_b1[i];
        s_rho_b1[i] = rho_b1[i];
        s_psi_b1[i] = psi_b1[i];
    }
    if (tid < 16) s_accinit[tid] = (float)NNB * phi_b2[tid] + (float)NOB * obs_b2[tid];
    if (tid < 2)  { s_rho_b2[tid] = rho_b2[tid]; s_psi_b2[tid] = psi_b2[tid]; }
    __syncthreads();

    const int idx = blockIdx.x * 256 + tid;
    if (idx >= BTOT) return;

    const float* xr = x + (long long)idx * DOBS;

    // acc = phi_sum + obs_sum (16-wide), biases pre-folded
    float acc[16];
    #pragma unroll
    for (int o = 0; o < 16; o++) acc[o] = s_accinit[o];

    float bar0 = 0.f, bar1 = 0.f;

    // ---- phi over 16 neighbors + barrier term -------------------------
    {
        const float4* w1t = (const float4*)s_phi_w1t;    // [j] -> 4 weights
        const float4* w2  = (const float4*)s_phi_w2;     // [j*4 + q]
        for (int n = 0; n < NNB; n++) {
            const float* sp = xr + NB_OFF + n * SDIM;
            float s0 = __ldg(sp + 0), s1 = __ldg(sp + 1);
            float s2 = __ldg(sp + 2), s3 = __ldg(sp + 3);

            // barrier: p = -s[0:2]; h = |p| - DS; bar += (gamma/h) * p
            float nrm  = sqrtf(fmaf(s0, s0, s1 * s1));
            float coef = GAM_C / (nrm - DS_C);
            bar0 -= coef * s0;
            bar1 -= coef * s1;

            #pragma unroll 4
            for (int j = 0; j < HID; j++) {
                float4 w = w1t[j];
                float  h = s_phi_b1[j];
                h = fmaf(s0, w.x, h);
                h = fmaf(s1, w.y, h);
                h = fmaf(s2, w.z, h);
                h = fmaf(s3, w.w, h);
                h = fmaxf(h, 0.f);
                #pragma unroll
                for (int q = 0; q < 4; q++) {
                    float4 v = w2[j * 4 + q];
                    acc[q * 4 + 0] = fmaf(h, v.x, acc[q * 4 + 0]);
                    acc[q * 4 + 1] = fmaf(h, v.y, acc[q * 4 + 1]);
                    acc[q * 4 + 2] = fmaf(h, v.z, acc[q * 4 + 2]);
                    acc[q * 4 + 3] = fmaf(h, v.w, acc[q * 4 + 3]);
                }
            }
        }
    }

    // ---- obs over 8 observations --------------------------------------
    {
        const float2* w1t = (const float2*)s_obs_w1t;
        const float4* w2  = (const float4*)s_obs_w2;
        for (int m = 0; m < NOB; m++) {
            float o0 = __ldg(xr + OB_OFF + 2 * m);
            float o1 = __ldg(xr + OB_OFF + 2 * m + 1);
            #pragma unroll 4
            for (int j = 0; j < HID; j++) {
                float2 w = w1t[j];
                float  h = fmaf(o0, w.x, fmaf(o1, w.y, s_obs_b1[j]));
                h = fmaxf(h, 0.f);
                #pragma unroll
                for (int q = 0; q < 4; q++) {
                    float4 v = w2[j * 4 + q];
                    acc[q * 4 + 0] = fmaf(h, v.x, acc[q * 4 + 0]);
                    acc[q * 4 + 1] = fmaf(h, v.y, acc[q * 4 + 1]);
                    acc[q * 4 + 2] = fmaf(h, v.z, acc[q * 4 + 2]);
                    acc[q * 4 + 3] = fmaf(h, v.w, acc[q * 4 + 3]);
                }
            }
        }
    }

    // ---- rho: 16 -> 64 -> 2 -------------------------------------------
    float r0 = s_rho_b2[0], r1 = s_rho_b2[1];
    {
        const float4* w1t = (const float4*)s_rho_w1t;    // [j*4 + q]
        #pragma unroll 4
        for (int j = 0; j < HID; j++) {
            float h = s_rho_b1[j];
            #pragma unroll
            for (int q = 0; q < 4; q++) {
                float4 w = w1t[j * 4 + q];
                h = fmaf(acc[q * 4 + 0], w.x, h);
                h = fmaf(acc[q * 4 + 1], w.y, h);
                h = fmaf(acc[q * 4 + 2], w.z, h);
                h = fmaf(acc[q * 4 + 3], w.w, h);
            }
            h = fmaxf(h, 0.f);
            r0 = fmaf(h, s_rho_w2[2 * j + 0], r0);
            r1 = fmaf(h, s_rho_w2[2 * j + 1], r1);
        }
    }

    // ---- psi: [rho0, rho1, g0, g1] -> 64 -> 2 -------------------------
    float g0 = __ldg(xr + 0), g1 = __ldg(xr + 1);
    float e0 = s_psi_b2[0], e1 = s_psi_b2[1];
    {
        const float4* w1t = (const float4*)s_psi_w1t;
        #pragma unroll 4
        for (int j = 0; j < HID; j++) {
            float4 w = w1t[j];
            float  h = s_psi_b1[j];
            h = fmaf(r0, w.x, h);
            h = fmaf(r1, w.y, h);
            h = fmaf(g0, w.z, h);
            h = fmaf(g1, w.w, h);
            h = fmaxf(h, 0.f);
            e0 = fmaf(h, s_psi_w2[2 * j + 0], e0);
            e1 = fmaf(h, s_psi_w2[2 * j + 1], e1);
        }
    }

    // empty = (tanh(e)+1)*0.5*(PHI_MAX-PHI_MIN)+PHI_MIN = tanh(e)  (range [-1,1])
    // action = tanh(empty + barrier)
    // out = (action+1)*0.5*(A_MAX-A_MIN)+A_MIN = 2*action           (range [-2,2])
    float a0 = tanhf(tanhf(e0) + bar0);
    float a1 = tanhf(tanhf(e1) + bar1);
    out[2 * idx + 0] = 2.f * a0;
    out[2 * idx + 1] = 2.f * a1;
}

extern "C" void kernel_launch(void* const* d_in, const int* in_sizes, int n_in,
                              void* d_out, int out_size)
{
    const float* x       = (const float*)d_in[0];
    const float* phi_w1  = (const float*)d_in[1];
    const float* phi_b1  = (const float*)d_in[2];
    const float* phi_w2  = (const float*)d_in[3];
    const float* phi_b2  = (const float*)d_in[4];
    const float* obs_w1  = (const float*)d_in[5];
    const float* obs_b1  = (const float*)d_in[6];
    const float* obs_w2  = (const float*)d_in[7];
    const float* obs_b2  = (const float*)d_in[8];
    const float* rho_w1  = (const float*)d_in[9];
    const float* rho_b1  = (const float*)d_in[10];
    const float* rho_w2  = (const float*)d_in[11];
    const float* rho_b2  = (const float*)d_in[12];
    const float* psi_w1  = (const float*)d_in[13];
    const float* psi_b1  = (const float*)d_in[14];
    const float* psi_w2  = (const float*)d_in[15];
    const float* psi_b2  = (const float*)d_in[16];
    float* out = (float*)d_out;

    const int grid = (BTOT + 255) / 256;   // 391
    barrier_net_kernel<<<grid, 256>>>(
        x,
        phi_w1, phi_b1, phi_w2, phi_b2,
        obs_w1, obs_b1, obs_w2, obs_b2,
        rho_w1, rho_b1, rho_w2, rho_b2,
        psi_w1, psi_b1, psi_w2, psi_b2,
        out);
}

// round 6
// speedup vs baseline: 3.2181x; 3.2181x over previous
#include <cuda_runtime.h>

// Problem constants (from reference)
#define BTOT   100000
#define NNB    16          // NN neighbors
#define NOB    8           // NO observations
#define SDIM   4           // SD
#define HID    64          // H
#define DOBS   85          // 1 + (NN+1)*SD + 2*NO
#define DS_C   0.2f
#define GAM_C  0.01f

#define NB_OFF 5           // 1 + SD
#define OB_OFF 69          // 1 + (NN+1)*SD

__global__ __launch_bounds__(256) void barrier_net_kernel(
    const float* __restrict__ x,
    const float* __restrict__ phi_w1, const float* __restrict__ phi_b1,
    const float* __restrict__ phi_w2, const float* __restrict__ phi_b2,
    const float* __restrict__ obs_w1, const float* __restrict__ obs_b1,
    const float* __restrict__ obs_w2, const float* __restrict__ obs_b2,
    const float* __restrict__ rho_w1, const float* __restrict__ rho_b1,
    const float* __restrict__ rho_w2, const float* __restrict__ rho_b2,
    const float* __restrict__ psi_w1, const float* __restrict__ psi_b1,
    const float* __restrict__ psi_w2, const float* __restrict__ psi_b2,
    float* __restrict__ out)
{
    // Shared weight staging. *_w1 transposed so each hidden unit's input
    // weights are one contiguous LDS.128/.64. *_w2 row-major (row j
    // contiguous over the 16 outputs).
    __shared__ __align__(16) float s_phi_w1t[HID * 4];   // [j][k]
    __shared__             float s_phi_b1 [HID];
    __shared__ __align__(16) float s_phi_w2 [HID * 16];  // [j][o]
    __shared__ __align__(16) float s_obs_w1t[HID * 2];   // [j][k]
    __shared__             float s_obs_b1 [HID];
    __shared__ __align__(16) float s_obs_w2 [HID * 16];
    __shared__ __align__(16) float s_rho_w1t[HID * 16];  // [j][k]
    __shared__             float s_rho_b1 [HID];
    __shared__ __align__(8)  float s_rho_w2 [HID * 2];
    __shared__ __align__(16) float s_psi_w1t[HID * 4];   // [j][k] = {rho0,rho1,g0,g1}
    __shared__             float s_psi_b1 [HID];
    __shared__ __align__(8)  float s_psi_w2 [HID * 2];
    __shared__             float s_accinit[16];          // NN*phi_b2 + NO*obs_b2
    __shared__             float s_rho_b2 [2];
    __shared__             float s_psi_b2 [2];

    const int tid = threadIdx.x;

    // Cooperative weight load + transpose (~4.3k floats)
    for (int i = tid; i < HID * 4; i += 256) {
        int j = i >> 2, k = i & 3;
        s_phi_w1t[i] = phi_w1[k * HID + j];
        s_psi_w1t[i] = psi_w1[k * HID + j];
    }
    for (int i = tid; i < HID * 2; i += 256) {
        int j = i >> 1, k = i & 1;
        s_obs_w1t[i] = obs_w1[k * HID + j];
        s_rho_w2[i]  = rho_w2[i];
        s_psi_w2[i]  = psi_w2[i];
    }
    for (int i = tid; i < HID * 16; i += 256) {
        int j = i >> 4, k = i & 15;
        s_rho_w1t[i] = rho_w1[k * HID + j];
        s_phi_w2[i]  = phi_w2[i];
        s_obs_w2[i]  = obs_w2[i];
    }
    for (int i = tid; i < HID; i += 256) {
        s_phi_b1[i] = phi_b1[i];
        s_obs_b1[i] = obs_b1[i];
        s_rho_b1[i] = rho_b1[i];
        s_psi_b1[i] = psi_b1[i];
    }
    if (tid < 16) s_accinit[tid] = (float)NNB * phi_b2[tid] + (float)NOB * obs_b2[tid];
    if (tid < 2)  { s_rho_b2[tid] = rho_b2[tid]; s_psi_b2[tid] = psi_b2[tid]; }
    __syncthreads();

    const int idx = blockIdx.x * 256 + tid;
    if (idx >= BTOT) return;

    const float* xr = x + (long long)idx * DOBS;

    // ---- stage the whole sample into registers ------------------------
    float n0[NNB], n1[NNB], n2[NNB], n3[NNB];
    #pragma unroll
    for (int n = 0; n < NNB; n++) {
        const float* sp = xr + NB_OFF + n * SDIM;
        n0[n] = __ldg(sp + 0);
        n1[n] = __ldg(sp + 1);
        n2[n] = __ldg(sp + 2);
        n3[n] = __ldg(sp + 3);
    }
    float o0[NOB], o1[NOB];
    #pragma unroll
    for (int m = 0; m < NOB; m++) {
        o0[m] = __ldg(xr + OB_OFF + 2 * m);
        o1[m] = __ldg(xr + OB_OFF + 2 * m + 1);
    }
    float g0 = __ldg(xr + 0), g1 = __ldg(xr + 1);

    // ---- barrier term -------------------------------------------------
    float bar0 = 0.f, bar1 = 0.f;
    #pragma unroll
    for (int n = 0; n < NNB; n++) {
        float nrm  = sqrtf(fmaf(n0[n], n0[n], n1[n] * n1[n]));
        float coef = GAM_C / (nrm - DS_C);
        bar0 -= coef * n0[n];
        bar1 -= coef * n1[n];
    }

    // acc = phi_sum + obs_sum (16-wide), output biases pre-folded
    float acc[16];
    #pragma unroll
    for (int o = 0; o < 16; o++) acc[o] = s_accinit[o];

    // ---- phi: j outer, neighbors inner (weights loaded ONCE per j) ----
    {
        const float4* w1t = (const float4*)s_phi_w1t;
        const float4* w2  = (const float4*)s_phi_w2;
        #pragma unroll 2
        for (int j = 0; j < HID; j++) {
            float4 w = w1t[j];
            float  b = s_phi_b1[j];
            float  hsA = 0.f, hsB = 0.f;
            #pragma unroll
            for (int n = 0; n < NNB; n += 2) {
                float ha = b, hb = b;
                ha = fmaf(n0[n],     w.x, ha);
                hb = fmaf(n0[n + 1], w.x, hb);
                ha = fmaf(n1[n],     w.y, ha);
                hb = fmaf(n1[n + 1], w.y, hb);
                ha = fmaf(n2[n],     w.z, ha);
                hb = fmaf(n2[n + 1], w.z, hb);
                ha = fmaf(n3[n],     w.w, ha);
                hb = fmaf(n3[n + 1], w.w, hb);
                hsA += fmaxf(ha, 0.f);
                hsB += fmaxf(hb, 0.f);
            }
            float hsum = hsA + hsB;
            #pragma unroll
            for (int q = 0; q < 4; q++) {
                float4 v = w2[j * 4 + q];
                acc[q * 4 + 0] = fmaf(hsum, v.x, acc[q * 4 + 0]);
                acc[q * 4 + 1] = fmaf(hsum, v.y, acc[q * 4 + 1]);
                acc[q * 4 + 2] = fmaf(hsum, v.z, acc[q * 4 + 2]);
                acc[q * 4 + 3] = fmaf(hsum, v.w, acc[q * 4 + 3]);
            }
        }
    }

    // ---- obs: j outer, observations inner -----------------------------
    {
        const float2* w1t = (const float2*)s_obs_w1t;
        const float4* w2  = (const float4*)s_obs_w2;
        #pragma unroll 2
        for (int j = 0; j < HID; j++) {
            float2 w = w1t[j];
            float  b = s_obs_b1[j];
            float  hsA = 0.f, hsB = 0.f;
            #pragma unroll
            for (int m = 0; m < NOB; m += 2) {
                float ha = fmaf(o0[m],     w.x, fmaf(o1[m],     w.y, b));
                float hb = fmaf(o0[m + 1], w.x, fmaf(o1[m + 1], w.y, b));
                hsA += fmaxf(ha, 0.f);
                hsB += fmaxf(hb, 0.f);
            }
            float hsum = hsA + hsB;
            #pragma unroll
            for (int q = 0; q < 4; q++) {
                float4 v = w2[j * 4 + q];
                acc[q * 4 + 0] = fmaf(hsum, v.x, acc[q * 4 + 0]);
                acc[q * 4 + 1] = fmaf(hsum, v.y, acc[q * 4 + 1]);
                acc[q * 4 + 2] = fmaf(hsum, v.z, acc[q * 4 + 2]);
                acc[q * 4 + 3] = fmaf(hsum, v.w, acc[q * 4 + 3]);
            }
        }
    }

    // ---- rho: 16 -> 64 -> 2 -------------------------------------------
    float r0 = s_rho_b2[0], r1 = s_rho_b2[1];
    {
        const float4* w1t = (const float4*)s_rho_w1t;    // [j*4 + q]
        #pragma unroll 4
        for (int j = 0; j < HID; j++) {
            float h = s_rho_b1[j];
            #pragma unroll
            for (int q = 0; q < 4; q++) {
                float4 w = w1t[j * 4 + q];
                h = fmaf(acc[q * 4 + 0], w.x, h);
                h = fmaf(acc[q * 4 + 1], w.y, h);
                h = fmaf(acc[q * 4 + 2], w.z, h);
                h = fmaf(acc[q * 4 + 3], w.w, h);
            }
            h = fmaxf(h, 0.f);
            r0 = fmaf(h, s_rho_w2[2 * j + 0], r0);
            r1 = fmaf(h, s_rho_w2[2 * j + 1], r1);
        }
    }

    // ---- psi: [rho0, rho1, g0, g1] -> 64 -> 2 -------------------------
    float e0 = s_psi_b2[0], e1 = s_psi_b2[1];
    {
        const float4* w1t = (const float4*)s_psi_w1t;
        #pragma unroll 4
        for (int j = 0; j < HID; j++) {
            float4 w = w1t[j];
            float  h = s_psi_b1[j];
            h = fmaf(r0, w.x, h);
            h = fmaf(r1, w.y, h);
            h = fmaf(g0, w.z, h);
            h = fmaf(g1, w.w, h);
            h = fmaxf(h, 0.f);
            e0 = fmaf(h, s_psi_w2[2 * j + 0], e0);
            e1 = fmaf(h, s_psi_w2[2 * j + 1], e1);
        }
    }

    // empty affine == tanh(e); final affine == 2*action
    float a0 = tanhf(tanhf(e0) + bar0);
    float a1 = tanhf(tanhf(e1) + bar1);
    out[2 * idx + 0] = 2.f * a0;
    out[2 * idx + 1] = 2.f * a1;
}

extern "C" void kernel_launch(void* const* d_in, const int* in_sizes, int n_in,
                              void* d_out, int out_size)
{
    const float* x       = (const float*)d_in[0];
    const float* phi_w1  = (const float*)d_in[1];
    const float* phi_b1  = (const float*)d_in[2];
    const float* phi_w2  = (const float*)d_in[3];
    const float* phi_b2  = (const float*)d_in[4];
    const float* obs_w1  = (const float*)d_in[5];
    const float* obs_b1  = (const float*)d_in[6];
    const float* obs_w2  = (const float*)d_in[7];
    const float* obs_b2  = (const float*)d_in[8];
    const float* rho_w1  = (const float*)d_in[9];
    const float* rho_b1  = (const float*)d_in[10];
    const float* rho_w2  = (const float*)d_in[11];
    const float* rho_b2  = (const float*)d_in[12];
    const float* psi_w1  = (const float*)d_in[13];
    const float* psi_b1  = (const float*)d_in[14];
    const float* psi_w2  = (const float*)d_in[15];
    const float* psi_b2  = (const float*)d_in[16];
    float* out = (float*)d_out;

    const int grid = (BTOT + 255) / 256;   // 391
    barrier_net_kernel<<<grid, 256>>>(
        x,
        phi_w1, phi_b1, phi_w2, phi_b2,
        obs_w1, obs_b1, obs_w2, obs_b2,
        rho_w1, rho_b1, rho_w2, rho_b2,
        psi_w1, psi_b1, psi_w2, psi_b2,
        out);
}

// round 7
// speedup vs baseline: 3.4191x; 1.0624x over previous
#include <cuda_runtime.h>

// Problem constants
#define BTOT   100000
#define NNB    16
#define NOB    8
#define SDIM   4
#define HID    64
#define DOBS   85
#define DS_C   0.2f
#define GAM_C  0.01f
#define NB_OFF 5
#define OB_OFF 69

typedef unsigned long long ull;

// ---- packed f32x2 helpers (SASS FFMA2 path) ---------------------------
__device__ __forceinline__ ull pk2(float lo, float hi) {
    ull r; asm("mov.b64 %0,{%1,%2};" : "=l"(r) : "f"(lo), "f"(hi)); return r;
}
__device__ __forceinline__ void up2(ull v, float& lo, float& hi) {
    asm("mov.b64 {%0,%1},%2;" : "=f"(lo), "=f"(hi) : "l"(v));
}
__device__ __forceinline__ ull fma2(ull a, ull b, ull c) {
    ull d; asm("fma.rn.f32x2 %0,%1,%2,%3;" : "=l"(d) : "l"(a), "l"(b), "l"(c)); return d;
}

__global__ __launch_bounds__(256) void barrier_net_kernel(
    const float* __restrict__ x,
    const float* __restrict__ phi_w1, const float* __restrict__ phi_b1,
    const float* __restrict__ phi_w2, const float* __restrict__ phi_b2,
    const float* __restrict__ obs_w1, const float* __restrict__ obs_b1,
    const float* __restrict__ obs_w2, const float* __restrict__ obs_b2,
    const float* __restrict__ rho_w1, const float* __restrict__ rho_b1,
    const float* __restrict__ rho_w2, const float* __restrict__ rho_b2,
    const float* __restrict__ psi_w1, const float* __restrict__ psi_b1,
    const float* __restrict__ psi_w2, const float* __restrict__ psi_b2,
    float* __restrict__ out)
{
    // Weight staging. w1 layers stored DUPLICATED per hidden unit:
    //   s_phi_w1d[j*8 + comp*2 + dup] = phi_w1[comp*HID + j]
    // so one ulonglong2 LDS.128 yields two packed (w,w) operands directly.
    __shared__ __align__(16) float s_phi_w1d[HID * 8];   // 512
    __shared__ __align__(8)  float s_phi_b1d[HID * 2];   // (b,b) pairs
    __shared__ __align__(16) float s_phi_w2 [HID * 16];
    __shared__ __align__(16) float s_obs_w1d[HID * 4];   // 256
    __shared__ __align__(8)  float s_obs_b1d[HID * 2];
    __shared__ __align__(16) float s_obs_w2 [HID * 16];
    __shared__ __align__(16) float s_rho_w1t[HID * 16];  // [j][k] transposed
    __shared__             float s_rho_b1 [HID];
    __shared__ __align__(8)  float s_rho_w2 [HID * 2];
    __shared__ __align__(16) float s_psi_w1t[HID * 4];   // [j][k] = {rho0,rho1,g0,g1}
    __shared__             float s_psi_b1 [HID];
    __shared__ __align__(8)  float s_psi_w2 [HID * 2];
    __shared__ __align__(16) float s_accinit[16];        // NN*phi_b2 + NO*obs_b2
    __shared__             float s_rho_b2 [2];
    __shared__             float s_psi_b2 [2];

    const int tid = threadIdx.x;

    // Cooperative staging
    for (int i = tid; i < HID * 8; i += 256) {           // phi w1 duplicated
        int j = i >> 3, c = (i >> 1) & 3;
        s_phi_w1d[i] = phi_w1[c * HID + j];
    }
    for (int i = tid; i < HID * 4; i += 256) {           // obs w1 duplicated, psi w1t
        int j = i >> 2, c = (i >> 1) & 1;
        s_obs_w1d[i] = obs_w1[c * HID + j];
        int j2 = i >> 2, k2 = i & 3;
        s_psi_w1t[i] = psi_w1[k2 * HID + j2];
    }
    for (int i = tid; i < HID * 2; i += 256) {           // duplicated biases, small w2s
        int j = i >> 1;
        s_phi_b1d[i] = phi_b1[j];
        s_obs_b1d[i] = obs_b1[j];
        s_rho_w2[i]  = rho_w2[i];
        s_psi_w2[i]  = psi_w2[i];
    }
    for (int i = tid; i < HID * 16; i += 256) {          // big mats
        int j = i >> 4, k = i & 15;
        s_rho_w1t[i] = rho_w1[k * HID + j];
        s_phi_w2[i]  = phi_w2[i];
        s_obs_w2[i]  = obs_w2[i];
    }
    for (int i = tid; i < HID; i += 256) {
        s_rho_b1[i] = rho_b1[i];
        s_psi_b1[i] = psi_b1[i];
    }
    if (tid < 16) s_accinit[tid] = (float)NNB * phi_b2[tid] + (float)NOB * obs_b2[tid];
    if (tid < 2)  { s_rho_b2[tid] = rho_b2[tid]; s_psi_b2[tid] = psi_b2[tid]; }
    __syncthreads();

    const int idx = blockIdx.x * 256 + tid;
    if (idx >= BTOT) return;

    const float* xr = x + (long long)idx * DOBS;

    // ---- stage sample: neighbors packed in pairs, barrier on the fly --
    ull pn0[8], pn1[8], pn2[8], pn3[8];
    float bar0 = 0.f, bar1 = 0.f;
    #pragma unroll
    for (int p = 0; p < 8; p++) {
        const float* sa = xr + NB_OFF + (2 * p) * SDIM;
        float a0 = __ldg(sa + 0), a1 = __ldg(sa + 1), a2 = __ldg(sa + 2), a3 = __ldg(sa + 3);
        float c0 = __ldg(sa + 4), c1 = __ldg(sa + 5), c2 = __ldg(sa + 6), c3 = __ldg(sa + 7);

        float na = sqrtf(fmaf(a0, a0, a1 * a1));
        float ka = GAM_C / (na - DS_C);
        bar0 -= ka * a0;  bar1 -= ka * a1;
        float nc = sqrtf(fmaf(c0, c0, c1 * c1));
        float kc = GAM_C / (nc - DS_C);
        bar0 -= kc * c0;  bar1 -= kc * c1;

        pn0[p] = pk2(a0, c0);
        pn1[p] = pk2(a1, c1);
        pn2[p] = pk2(a2, c2);
        pn3[p] = pk2(a3, c3);
    }
    ull pm0[4], pm1[4];
    #pragma unroll
    for (int p = 0; p < 4; p++) {
        const float* oa = xr + OB_OFF + 4 * p;
        pm0[p] = pk2(__ldg(oa + 0), __ldg(oa + 2));
        pm1[p] = pk2(__ldg(oa + 1), __ldg(oa + 3));
    }
    float g0 = __ldg(xr + 0), g1 = __ldg(xr + 1);

    // acc packed: accp[t] = (acc_{2t}, acc_{2t+1}); output biases pre-folded
    ull accp[8];
    {
        const ull* ai = (const ull*)s_accinit;
        #pragma unroll
        for (int t = 0; t < 8; t++) accp[t] = ai[t];
    }
    const ull ZERO2 = 0ull;

    // ---- phi: j outer; 2 neighbors per FFMA2 --------------------------
    {
        const ulonglong2* w1d = (const ulonglong2*)s_phi_w1d;
        const ull*        bd  = (const ull*)s_phi_b1d;
        const ulonglong2* w2p = (const ulonglong2*)s_phi_w2;
        #pragma unroll 2
        for (int j = 0; j < HID; j++) {
            ulonglong2 wa = w1d[2 * j + 0];   // (wx,wx),(wy,wy)
            ulonglong2 wb = w1d[2 * j + 1];   // (wz,wz),(ww,ww)
            ull bb = bd[j];
            float hsA = 0.f, hsB = 0.f;
            #pragma unroll
            for (int p = 0; p < 8; p++) {
                ull h = fma2(pn0[p], wa.x, bb);
                h = fma2(pn1[p], wa.y, h);
                h = fma2(pn2[p], wb.x, h);
                h = fma2(pn3[p], wb.y, h);
                float hx, hy; up2(h, hx, hy);
                hsA += fmaxf(hx, 0.f);
                hsB += fmaxf(hy, 0.f);
            }
            float hsum = hsA + hsB;
            ull hd = pk2(hsum, hsum);
            #pragma unroll
            for (int q = 0; q < 4; q++) {
                ulonglong2 v = w2p[j * 4 + q];
                accp[2 * q + 0] = fma2(hd, v.x, accp[2 * q + 0]);
                accp[2 * q + 1] = fma2(hd, v.y, accp[2 * q + 1]);
            }
        }
    }

    // ---- obs: j outer; 2 observations per FFMA2 -----------------------
    {
        const ulonglong2* w1d = (const ulonglong2*)s_obs_w1d;  // (wx,wx),(wy,wy)
        const ull*        bd  = (const ull*)s_obs_b1d;
        const ulonglong2* w2p = (const ulonglong2*)s_obs_w2;
        #pragma unroll 2
        for (int j = 0; j < HID; j++) {
            ulonglong2 w = w1d[j];
            ull bb = bd[j];
            float hsA = 0.f, hsB = 0.f;
            #pragma unroll
            for (int p = 0; p < 4; p++) {
                ull h = fma2(pm0[p], w.x, bb);
                h = fma2(pm1[p], w.y, h);
                float hx, hy; up2(h, hx, hy);
                hsA += fmaxf(hx, 0.f);
                hsB += fmaxf(hy, 0.f);
            }
            float hsum = hsA + hsB;
            ull hd = pk2(hsum, hsum);
            #pragma unroll
            for (int q = 0; q < 4; q++) {
                ulonglong2 v = w2p[j * 4 + q];
                accp[2 * q + 0] = fma2(hd, v.x, accp[2 * q + 0]);
                accp[2 * q + 1] = fma2(hd, v.y, accp[2 * q + 1]);
            }
        }
    }

    // ---- rho: 16 -> 64 -> 2 (packed 16-dot) ---------------------------
    float r0 = s_rho_b2[0], r1 = s_rho_b2[1];
    {
        #pragma unroll 2
        for (int j = 0; j < HID; j++) {
            const ulonglong2* rw = (const ulonglong2*)(s_rho_w1t + j * 16);
            ulonglong2 v0 = rw[0], v1 = rw[1], v2 = rw[2], v3 = rw[3];
            ull hp = fma2(accp[0], v0.x, ZERO2);
            hp = fma2(accp[1], v0.y, hp);
            hp = fma2(accp[2], v1.x, hp);
            hp = fma2(accp[3], v1.y, hp);
            hp = fma2(accp[4], v2.x, hp);
            hp = fma2(accp[5], v2.y, hp);
            hp = fma2(accp[6], v3.x, hp);
            hp = fma2(accp[7], v3.y, hp);
            float hx, hy; up2(hp, hx, hy);
            float h = fmaxf(hx + hy + s_rho_b1[j], 0.f);
            r0 = fmaf(h, s_rho_w2[2 * j + 0], r0);
            r1 = fmaf(h, s_rho_w2[2 * j + 1], r1);
        }
    }

    // ---- psi: [rho0,rho1,g0,g1] -> 64 -> 2 ----------------------------
    float e0 = s_psi_b2[0], e1 = s_psi_b2[1];
    {
        ull rg0 = pk2(r0, r1);
        ull rg1 = pk2(g0, g1);
        const ulonglong2* pw = (const ulonglong2*)s_psi_w1t;
        #pragma unroll 4
        for (int j = 0; j < HID; j++) {
            ulonglong2 w = pw[j];   // (wx,wy),(wz,ww)
            ull hp = fma2(rg0, w.x, ZERO2);
            hp = fma2(rg1, w.y, hp);
            float hx, hy; up2(hp, hx, hy);
            float h = fmaxf(hx + hy + s_psi_b1[j], 0.f);
            e0 = fmaf(h, s_psi_w2[2 * j + 0], e0);
            e1 = fmaf(h, s_psi_w2[2 * j + 1], e1);
        }
    }

    // empty affine == tanh(e); final affine == 2*action
    float a0 = tanhf(tanhf(e0) + bar0);
    float a1 = tanhf(tanhf(e1) + bar1);
    ((float2*)out)[idx] = make_float2(2.f * a0, 2.f * a1);
}

extern "C" void kernel_launch(void* const* d_in, const int* in_sizes, int n_in,
                              void* d_out, int out_size)
{
    const float* x       = (const float*)d_in[0];
    const float* phi_w1  = (const float*)d_in[1];
    const float* phi_b1  = (const float*)d_in[2];
    const float* phi_w2  = (const float*)d_in[3];
    const float* phi_b2  = (const float*)d_in[4];
    const float* obs_w1  = (const float*)d_in[5];
    const float* obs_b1  = (const float*)d_in[6];
    const float* obs_w2  = (const float*)d_in[7];
    const float* obs_b2  = (const float*)d_in[8];
    const float* rho_w1  = (const float*)d_in[9];
    const float* rho_b1  = (const float*)d_in[10];
    const float* rho_w2  = (const float*)d_in[11];
    const float* rho_b2  = (const float*)d_in[12];
    const float* psi_w1  = (const float*)d_in[13];
    const float* psi_b1  = (const float*)d_in[14];
    const float* psi_w2  = (const float*)d_in[15];
    const float* psi_b2  = (const float*)d_in[16];
    float* out = (float*)d_out;

    const int grid = (BTOT + 255) / 256;   // 391
    barrier_net_kernel<<<grid, 256>>>(
        x,
        phi_w1, phi_b1, phi_w2, phi_b2,
        obs_w1, obs_b1, obs_w2, obs_b2,
        rho_w1, rho_b1, rho_w2, rho_b2,
        psi_w1, psi_b1, psi_w2, psi_b2,
        out);
}